// round 10
// baseline (speedup 1.0000x reference)
#include <cuda_runtime.h>
#include <math.h>

// Problem shape (fixed by dataset): N=100000, H=32, K=15, C_in=C_out=64
#define MAXN 100000
#define NB_H 32
#define KPTS 15
#define CH   64

#define NBLOCKS       592                // 148 SMs x 4 (co-resident via __launch_bounds__(256,4))
#define NTHREADS      256
#define TOTAL_THREADS (NBLOCKS * NTHREADS)
#define TOTAL_WARPS   (NBLOCKS * 8)

// Scratch (__device__ globals: allocation-free rule)
__device__ float4 g_pts4[MAXN];      // s_pts packed as float4 (w unused)
__device__ float  g_val[MAXN * CH];  // raw kpconv rows for flagged points
__device__ int    g_flag[MAXN];      // 1 if candidate row
__device__ float  g_sum[CH];
__device__ float  g_sumsq[CH];
// software grid barrier (self-resetting, safe across graph replays)
__device__ int          g_bar_count = 0;
__device__ volatile int g_bar_gen   = 0;

static __host__ __device__ __forceinline__ float kp_extent() {
    return (float)(0.1 * 1.2 / 2.5);
}

static __device__ __forceinline__ void grid_sync() {
    __threadfence();
    __syncthreads();
    if (threadIdx.x == 0) {
        const int gen = g_bar_gen;
        if (atomicAdd(&g_bar_count, 1) == NBLOCKS - 1) {
            g_bar_count = 0;
            __threadfence();
            g_bar_gen = gen + 1;
        } else {
            while (g_bar_gen == gen) { __nanosleep(32); }
        }
    }
    __syncthreads();
}

__global__ void __launch_bounds__(NTHREADS, 4) fused_kernel(
    const float* __restrict__ q_pts,
    const float* __restrict__ s_pts,
    const int*   __restrict__ inds,
    const float* __restrict__ x,
    const float* __restrict__ kp,
    const float* __restrict__ W,    // [K, C, C]
    float* __restrict__ out, int N)
{
    __shared__ float sw[8][KPTS][CH];        // 30 KB, heavy-phase staging
    __shared__ float mm[CH], iv[CH], zz[CH]; // phase-C stats

    const int tid   = threadIdx.x;
    const int warp  = tid >> 5;
    const int lane  = tid & 31;
    const int gtid  = blockIdx.x * NTHREADS + tid;
    const int gwarp = blockIdx.x * 8 + warp;
    const unsigned FULL = 0xffffffffu;

    // conservative candidate threshold^2 (broadcast L1/L2 loads)
    float thr2;
    {
        float mx2 = 0.0f;
#pragma unroll
        for (int k = 0; k < KPTS; k++) {
            const float a = __ldg(kp + 3*k), b = __ldg(kp + 3*k + 1), c = __ldg(kp + 3*k + 2);
            mx2 = fmaxf(mx2, fmaf(a, a, fmaf(b, b, c * c)));
        }
        const float t = (kp_extent() + sqrtf(mx2)) * 1.0002f + 1e-6f;  // false positives ok
        thr2 = t * t;
    }

    // ---------------- Phase A: pack s_pts (vectorized), zero flags/sums ----------------
    {
        const float4* __restrict__ s4 = reinterpret_cast<const float4*>(s_pts);
        const int nq = N >> 2;   // groups of 4 points (N=100000 -> 25000, no tail)
        for (int i = gtid; i < nq; i += TOTAL_THREADS) {
            const float4 a = __ldg(s4 + (long)i * 3);
            const float4 b = __ldg(s4 + (long)i * 3 + 1);
            const float4 c = __ldg(s4 + (long)i * 3 + 2);
            const int p = i << 2;
            g_pts4[p]     = make_float4(a.x, a.y, a.z, 0.0f);
            g_pts4[p + 1] = make_float4(a.w, b.x, b.y, 0.0f);
            g_pts4[p + 2] = make_float4(b.z, b.w, c.x, 0.0f);
            g_pts4[p + 3] = make_float4(c.y, c.z, c.w, 0.0f);
            *reinterpret_cast<int4*>(&g_flag[p]) = make_int4(0, 0, 0, 0);
        }
        for (int i = (nq << 2) + gtid; i < N; i += TOTAL_THREADS) {   // generic tail
            g_flag[i] = 0;
            g_pts4[i] = make_float4(__ldg(s_pts + 3*i), __ldg(s_pts + 3*i + 1),
                                    __ldg(s_pts + 3*i + 2), 0.0f);
        }
        if (blockIdx.x == 0 && tid < CH) { g_sum[tid] = 0.0f; g_sumsq[tid] = 0.0f; }
    }
    grid_sync();

    // ------- Phase B: detect. 4 threads/point, 8 gathers in flight, flags only -------
    {
        const int total = N * 4;   // 4 sub-threads per point, 8 neighbors each
        for (int g = gtid; g < total; g += TOTAL_THREADS) {
            const int n   = g >> 2;
            const int sub = g & 3;

            const float qx = __ldg(q_pts + 3*n);
            const float qy = __ldg(q_pts + 3*n + 1);
            const float qz = __ldg(q_pts + 3*n + 2);

            const int4 a = __ldg(reinterpret_cast<const int4*>(inds) + (long)n * 8 + sub * 2);
            const int4 b = __ldg(reinterpret_cast<const int4*>(inds) + (long)n * 8 + sub * 2 + 1);

            // dataset guarantees idx in [0, N): 8 independent gathers (MLP=8)
            const float4 p0 = __ldg(&g_pts4[a.x]);
            const float4 p1 = __ldg(&g_pts4[a.y]);
            const float4 p2 = __ldg(&g_pts4[a.z]);
            const float4 p3 = __ldg(&g_pts4[a.w]);
            const float4 p4 = __ldg(&g_pts4[b.x]);
            const float4 p5 = __ldg(&g_pts4[b.y]);
            const float4 p6 = __ldg(&g_pts4[b.z]);
            const float4 p7 = __ldg(&g_pts4[b.w]);

            float dx, dy, dz;
            bool any = false;
            dx = p0.x - qx; dy = p0.y - qy; dz = p0.z - qz;
            any |= (fmaf(dx, dx, fmaf(dy, dy, dz * dz)) < thr2);
            dx = p1.x - qx; dy = p1.y - qy; dz = p1.z - qz;
            any |= (fmaf(dx, dx, fmaf(dy, dy, dz * dz)) < thr2);
            dx = p2.x - qx; dy = p2.y - qy; dz = p2.z - qz;
            any |= (fmaf(dx, dx, fmaf(dy, dy, dz * dz)) < thr2);
            dx = p3.x - qx; dy = p3.y - qy; dz = p3.z - qz;
            any |= (fmaf(dx, dx, fmaf(dy, dy, dz * dz)) < thr2);
            dx = p4.x - qx; dy = p4.y - qy; dz = p4.z - qz;
            any |= (fmaf(dx, dx, fmaf(dy, dy, dz * dz)) < thr2);
            dx = p5.x - qx; dy = p5.y - qy; dz = p5.z - qz;
            any |= (fmaf(dx, dx, fmaf(dy, dy, dz * dz)) < thr2);
            dx = p6.x - qx; dy = p6.y - qy; dz = p6.z - qz;
            any |= (fmaf(dx, dx, fmaf(dy, dy, dz * dz)) < thr2);
            dx = p7.x - qx; dy = p7.y - qy; dz = p7.z - qz;
            any |= (fmaf(dx, dx, fmaf(dy, dy, dz * dz)) < thr2);

            if (any) g_flag[n] = 1;   // racy same-value store: benign
        }
    }
    grid_sync();

    // ---------------- Phase B2: heavy. ballot-scan flags, exact KPConv per hit ----------------
    {
        const float EXT  = kp_extent();
        const float EXT2 = EXT * EXT;
        const float INVE = 1.0f / EXT;

        const int ngrp = (N + 31) >> 5;
        for (int g = gwarp; g < ngrp; g += TOTAL_WARPS) {
            const int fn = g * 32 + lane;
            const int f = (fn < N) ? g_flag[fn] : 0;
            unsigned hits = __ballot_sync(FULL, f != 0);

            while (hits) {
                const int bit = __ffs(hits) - 1;
                hits &= (hits - 1);
                const int n = g * 32 + bit;

                const float qx = __ldg(q_pts + 3*n);
                const float qy = __ldg(q_pts + 3*n + 1);
                const float qz = __ldg(q_pts + 3*n + 2);

                const int idx = __ldg(inds + (long)n * NB_H + lane);
                const bool valid = ((unsigned)idx < (unsigned)N);
                float nx = 1e9f, ny = 1e9f, nz = 1e9f;
                if (valid) {
                    const float4 p = __ldg(&g_pts4[idx]);
                    nx = p.x - qx; ny = p.y - qy; nz = p.z - qz;
                }
                const float r2 = fmaf(nx, nx, fmaf(ny, ny, nz * nz));
                unsigned mask = __ballot_sync(FULL, valid && (r2 < thr2));

                float acc0[KPTS], acc1[KPTS];
#pragma unroll
                for (int k = 0; k < KPTS; k++) { acc0[k] = 0.0f; acc1[k] = 0.0f; }

                unsigned m = mask;
                while (m) {
                    const int hs = __ffs(m) - 1;
                    m &= (m - 1);
                    const int   sidx = __shfl_sync(FULL, idx, hs);
                    const float bx = __shfl_sync(FULL, nx, hs);
                    const float by = __shfl_sync(FULL, ny, hs);
                    const float bz = __shfl_sync(FULL, nz, hs);
                    const float xv0 = __ldg(x + (long)sidx * CH + lane);
                    const float xv1 = __ldg(x + (long)sidx * CH + lane + 32);
#pragma unroll
                    for (int k = 0; k < KPTS; k++) {
                        const float dx = bx - __ldg(kp + 3*k);
                        const float dy = by - __ldg(kp + 3*k + 1);
                        const float dz = bz - __ldg(kp + 3*k + 2);
                        const float d2 = fmaf(dx, dx, fmaf(dy, dy, dz * dz));
                        if (d2 < EXT2) {
                            const float w = fmaxf(1.0f - sqrtf(d2) * INVE, 0.0f);
                            acc0[k] = fmaf(w, xv0, acc0[k]);
                            acc1[k] = fmaf(w, xv1, acc1[k]);
                        }
                    }
                }

                unsigned kmask = 0;
#pragma unroll
                for (int k = 0; k < KPTS; k++) {
                    sw[warp][k][lane]      = acc0[k];
                    sw[warp][k][lane + 32] = acc1[k];
                    if (__ballot_sync(FULL, (acc0[k] != 0.0f) || (acc1[k] != 0.0f)))
                        kmask |= (1u << k);
                }
                __syncwarp();

                float o0 = 0.0f, o1 = 0.0f;
                for (int k = 0; k < KPTS; k++) {
                    if (!(kmask & (1u << k))) continue;
                    const float* Wk = W + (long)k * CH * CH;
#pragma unroll 8
                    for (int c = 0; c < CH; c++) {
                        const float wv = sw[warp][k][c];
                        o0 = fmaf(wv, __ldg(Wk + c * CH + lane),      o0);
                        o1 = fmaf(wv, __ldg(Wk + c * CH + lane + 32), o1);
                    }
                }
                __syncwarp();

                g_val[(long)n * CH + lane]      = o0;
                g_val[(long)n * CH + lane + 32] = o1;
                atomicAdd(&g_sum[lane],        o0);
                atomicAdd(&g_sum[lane + 32],   o1);
                atomicAdd(&g_sumsq[lane],      o0 * o0);
                atomicAdd(&g_sumsq[lane + 32], o1 * o1);
            }
        }
    }
    grid_sync();

    // ---------------- Phase C: finalize stats, stream output ----------------
    if (tid < CH) {
        const float invN = 1.0f / (float)N;
        const float mean = g_sum[tid] * invN;
        const float var  = fmaxf(g_sumsq[tid] * invN - mean * mean, 0.0f);
        const float inv  = rsqrtf(var + 1e-5f);
        const float z    = (0.0f - mean) * inv;
        mm[tid] = mean;
        iv[tid] = inv;
        zz[tid] = (z >= 0.0f) ? z : 0.1f * z;
    }
    __syncthreads();

    {
        float4* __restrict__ out4 = reinterpret_cast<float4*>(out);
        const int c4 = (lane & 15) * 4;
        const float4 vz = make_float4(zz[c4], zz[c4 + 1], zz[c4 + 2], zz[c4 + 3]);
        const int ngrp = (N + 31) >> 5;   // 32-row groups

        for (int g = gwarp; g < ngrp; g += TOTAL_WARPS) {
            const int r0 = g * 32;
            const int fn = r0 + lane;
            const int f  = (fn < N) ? g_flag[fn] : 0;   // one coalesced load per warp
            const unsigned hits = __ballot_sync(FULL, f != 0);

            if (hits == 0 && r0 + 32 <= N) {
                const long base = (long)g * 512;        // float4 units (32 rows * 16)
#pragma unroll
                for (int j = 0; j < 16; j++)
                    out4[base + j * 32 + lane] = vz;
            } else {
                const int rend = min(r0 + 32, N);
                for (int r = r0; r < rend; r++) {
                    const int fr = __shfl_sync(FULL, f, r - r0);
                    float a0, a1;
                    if (fr) {
                        const float v0 = g_val[(long)r * CH + lane];
                        const float v1 = g_val[(long)r * CH + lane + 32];
                        a0 = (v0 - mm[lane])      * iv[lane];
                        a1 = (v1 - mm[lane + 32]) * iv[lane + 32];
                        a0 = (a0 >= 0.0f) ? a0 : 0.1f * a0;
                        a1 = (a1 >= 0.0f) ? a1 : 0.1f * a1;
                    } else {
                        a0 = zz[lane];
                        a1 = zz[lane + 32];
                    }
                    out[(long)r * CH + lane]      = a0;
                    out[(long)r * CH + lane + 32] = a1;
                }
            }
        }
    }
}

// ---------------- launch: ONE kernel ----------------
extern "C" void kernel_launch(void* const* d_in, const int* in_sizes, int n_in,
                              void* d_out, int out_size) {
    const float* q_pts = (const float*)d_in[0];
    const float* s_pts = (const float*)d_in[1];
    const int*   inds  = (const int*)  d_in[2];
    const float* x     = (const float*)d_in[3];
    const float* kp    = (const float*)d_in[4];
    const float* W     = (const float*)d_in[5];
    float* out = (float*)d_out;

    const int N = in_sizes[0] / 3;

    fused_kernel<<<NBLOCKS, NTHREADS>>>(q_pts, s_pts, inds, x, kp, W, out, N);
}

// round 12
// speedup vs baseline: 1.0335x; 1.0335x over previous
#include <cuda_runtime.h>
#include <cuda_fp16.h>
#include <math.h>

// Problem shape (fixed by dataset): N=100000, H=32, K=15, C_in=C_out=64
#define MAXN 100000
#define NB_H 32
#define KPTS 15
#define CH   64

#define NBLOCKS       592                // 148 SMs x 4 (co-resident via __launch_bounds__(256,4))
#define NTHREADS      256
#define TOTAL_THREADS (NBLOCKS * NTHREADS)
#define TOTAL_WARPS   (NBLOCKS * 8)

// Scratch (__device__ globals: allocation-free rule)
__device__ uint2  g_ptsh[MAXN];      // s_pts packed as 4x half (x,y | z,0) = 8 bytes
__device__ float  g_val[MAXN * CH];  // raw kpconv rows for flagged points
__device__ int    g_flag[MAXN];      // 1 if candidate row
__device__ float  g_sum[CH];
__device__ float  g_sumsq[CH];
// software grid barrier (self-resetting, safe across graph replays)
__device__ int          g_bar_count = 0;
__device__ volatile int g_bar_gen   = 0;

static __host__ __device__ __forceinline__ float kp_extent() {
    return (float)(0.1 * 1.2 / 2.5);
}

static __device__ __forceinline__ void grid_sync() {
    __threadfence();
    __syncthreads();
    if (threadIdx.x == 0) {
        const int gen = g_bar_gen;
        if (atomicAdd(&g_bar_count, 1) == NBLOCKS - 1) {
            g_bar_count = 0;
            __threadfence();
            g_bar_gen = gen + 1;
        } else {
            while (g_bar_gen == gen) { __nanosleep(32); }
        }
    }
    __syncthreads();
}

static __device__ __forceinline__ uint2 pack_half4(float x, float y, float z) {
    __half2 a = __floats2half2_rn(x, y);
    __half2 b = __floats2half2_rn(z, 0.0f);
    uint2 r;
    r.x = *reinterpret_cast<unsigned*>(&a);
    r.y = *reinterpret_cast<unsigned*>(&b);
    return r;
}

// squared distance (fp32) between packed half point p and fp32 query (qx,qy,qz)
static __device__ __forceinline__ float hdist2(uint2 p, float qx, float qy, float qz) {
    const float2 xy = __half22float2(*reinterpret_cast<__half2*>(&p.x));
    const float2 z_ = __half22float2(*reinterpret_cast<__half2*>(&p.y));
    const float dx = xy.x - qx, dy = xy.y - qy, dz = z_.x - qz;
    return fmaf(dx, dx, fmaf(dy, dy, dz * dz));
}

__global__ void __launch_bounds__(NTHREADS, 4) fused_kernel(
    const float* __restrict__ q_pts,
    const float* __restrict__ s_pts,
    const int*   __restrict__ inds,
    const float* __restrict__ x,
    const float* __restrict__ kp,
    const float* __restrict__ W,    // [K, C, C]
    float* __restrict__ out, int N)
{
    __shared__ float sw[8][KPTS][CH];        // 30 KB, heavy-phase staging
    __shared__ float mm[CH], iv[CH], zz[CH]; // phase-C stats

    const int tid   = threadIdx.x;
    const int warp  = tid >> 5;
    const int lane  = tid & 31;
    const int gtid  = blockIdx.x * NTHREADS + tid;
    const int gwarp = blockIdx.x * 8 + warp;
    const unsigned FULL = 0xffffffffu;

    // conservative candidate threshold^2; +0.01 covers fp16 storage error (<=0.0034)
    float thr2;
    {
        float mx2 = 0.0f;
#pragma unroll
        for (int k = 0; k < KPTS; k++) {
            const float a = __ldg(kp + 3*k), b = __ldg(kp + 3*k + 1), c = __ldg(kp + 3*k + 2);
            mx2 = fmaxf(mx2, fmaf(a, a, fmaf(b, b, c * c)));
        }
        const float t = (kp_extent() + sqrtf(mx2)) * 1.0002f + 0.01f;  // false positives ok
        thr2 = t * t;
    }

    // ---------------- Phase A: pack s_pts -> half4 (vectorized), zero flags/sums ----------------
    {
        const float4* __restrict__ s4 = reinterpret_cast<const float4*>(s_pts);
        const int nq = N >> 2;   // groups of 4 points (100000 -> 25000, no tail)
        for (int i = gtid; i < nq; i += TOTAL_THREADS) {
            const float4 a = __ldg(s4 + (long)i * 3);
            const float4 b = __ldg(s4 + (long)i * 3 + 1);
            const float4 c = __ldg(s4 + (long)i * 3 + 2);
            const int p = i << 2;
            g_ptsh[p]     = pack_half4(a.x, a.y, a.z);
            g_ptsh[p + 1] = pack_half4(a.w, b.x, b.y);
            g_ptsh[p + 2] = pack_half4(b.z, b.w, c.x);
            g_ptsh[p + 3] = pack_half4(c.y, c.z, c.w);
            *reinterpret_cast<int4*>(&g_flag[p]) = make_int4(0, 0, 0, 0);
        }
        for (int i = (nq << 2) + gtid; i < N; i += TOTAL_THREADS) {   // generic tail
            g_flag[i] = 0;
            g_ptsh[i] = pack_half4(__ldg(s_pts + 3*i), __ldg(s_pts + 3*i + 1),
                                   __ldg(s_pts + 3*i + 2));
        }
        if (blockIdx.x == 0 && tid < CH) { g_sum[tid] = 0.0f; g_sumsq[tid] = 0.0f; }
    }
    grid_sync();

    // ------- Phase B: detect. thread-per-quad (MLP=4), 8-byte gathers, flags only -------
    {
        const int nquad = N * (NB_H / 4);   // 800000 int4 quads
        for (int t = gtid; t < nquad; t += TOTAL_THREADS) {
            const int n = t >> 3;           // 8 quads per point
            const float qx = __ldg(q_pts + 3*n);
            const float qy = __ldg(q_pts + 3*n + 1);
            const float qz = __ldg(q_pts + 3*n + 2);

            const int4 iv4 = __ldg(reinterpret_cast<const int4*>(inds) + t);

            bool any = false;
            {
                const int id = iv4.x;
                if ((unsigned)id < (unsigned)N)
                    any |= (hdist2(__ldg(&g_ptsh[id]), qx, qy, qz) < thr2);
            }
            {
                const int id = iv4.y;
                if ((unsigned)id < (unsigned)N)
                    any |= (hdist2(__ldg(&g_ptsh[id]), qx, qy, qz) < thr2);
            }
            {
                const int id = iv4.z;
                if ((unsigned)id < (unsigned)N)
                    any |= (hdist2(__ldg(&g_ptsh[id]), qx, qy, qz) < thr2);
            }
            {
                const int id = iv4.w;
                if ((unsigned)id < (unsigned)N)
                    any |= (hdist2(__ldg(&g_ptsh[id]), qx, qy, qz) < thr2);
            }
            if (any) g_flag[n] = 1;         // racy same-value store: benign
        }
    }
    grid_sync();

    // ---------------- Phase B2: heavy. ballot-scan flags, exact KPConv per hit ----------------
    // Exact path uses the ORIGINAL fp32 s_pts (half packing only gates candidacy).
    {
        const float EXT  = kp_extent();
        const float EXT2 = EXT * EXT;
        const float INVE = 1.0f / EXT;

        const int ngrp = (N + 31) >> 5;
        for (int g = gwarp; g < ngrp; g += TOTAL_WARPS) {
            const int fn = g * 32 + lane;
            const int f = (fn < N) ? g_flag[fn] : 0;
            unsigned hits = __ballot_sync(FULL, f != 0);

            while (hits) {
                const int bit = __ffs(hits) - 1;
                hits &= (hits - 1);
                const int n = g * 32 + bit;

                const float qx = __ldg(q_pts + 3*n);
                const float qy = __ldg(q_pts + 3*n + 1);
                const float qz = __ldg(q_pts + 3*n + 2);

                const int idx = __ldg(inds + (long)n * NB_H + lane);
                const bool valid = ((unsigned)idx < (unsigned)N);
                float nx = 1e9f, ny = 1e9f, nz = 1e9f;
                if (valid) {
                    nx = __ldg(s_pts + 3*idx)     - qx;
                    ny = __ldg(s_pts + 3*idx + 1) - qy;
                    nz = __ldg(s_pts + 3*idx + 2) - qz;
                }
                const float r2 = fmaf(nx, nx, fmaf(ny, ny, nz * nz));
                unsigned mask = __ballot_sync(FULL, valid && (r2 < thr2));

                float acc0[KPTS], acc1[KPTS];
#pragma unroll
                for (int k = 0; k < KPTS; k++) { acc0[k] = 0.0f; acc1[k] = 0.0f; }

                unsigned m = mask;
                while (m) {
                    const int hs = __ffs(m) - 1;
                    m &= (m - 1);
                    const int   sidx = __shfl_sync(FULL, idx, hs);
                    const float bx = __shfl_sync(FULL, nx, hs);
                    const float by = __shfl_sync(FULL, ny, hs);
                    const float bz = __shfl_sync(FULL, nz, hs);
                    const float xv0 = __ldg(x + (long)sidx * CH + lane);
                    const float xv1 = __ldg(x + (long)sidx * CH + lane + 32);
#pragma unroll
                    for (int k = 0; k < KPTS; k++) {
                        const float dx = bx - __ldg(kp + 3*k);
                        const float dy = by - __ldg(kp + 3*k + 1);
                        const float dz = bz - __ldg(kp + 3*k + 2);
                        const float d2 = fmaf(dx, dx, fmaf(dy, dy, dz * dz));
                        if (d2 < EXT2) {
                            const float w = fmaxf(1.0f - sqrtf(d2) * INVE, 0.0f);
                            acc0[k] = fmaf(w, xv0, acc0[k]);
                            acc1[k] = fmaf(w, xv1, acc1[k]);
                        }
                    }
                }

                unsigned kmask = 0;
#pragma unroll
                for (int k = 0; k < KPTS; k++) {
                    sw[warp][k][lane]      = acc0[k];
                    sw[warp][k][lane + 32] = acc1[k];
                    if (__ballot_sync(FULL, (acc0[k] != 0.0f) || (acc1[k] != 0.0f)))
                        kmask |= (1u << k);
                }
                __syncwarp();

                float o0 = 0.0f, o1 = 0.0f;
                for (int k = 0; k < KPTS; k++) {
                    if (!(kmask & (1u << k))) continue;
                    const float* Wk = W + (long)k * CH * CH;
#pragma unroll 8
                    for (int c = 0; c < CH; c++) {
                        const float wv = sw[warp][k][c];
                        o0 = fmaf(wv, __ldg(Wk + c * CH + lane),      o0);
                        o1 = fmaf(wv, __ldg(Wk + c * CH + lane + 32), o1);
                    }
                }
                __syncwarp();

                g_val[(long)n * CH + lane]      = o0;
                g_val[(long)n * CH + lane + 32] = o1;
                atomicAdd(&g_sum[lane],        o0);
                atomicAdd(&g_sum[lane + 32],   o1);
                atomicAdd(&g_sumsq[lane],      o0 * o0);
                atomicAdd(&g_sumsq[lane + 32], o1 * o1);
            }
        }
    }
    grid_sync();

    // ---------------- Phase C: finalize stats, stream output ----------------
    if (tid < CH) {
        const float invN = 1.0f / (float)N;
        const float mean = g_sum[tid] * invN;
        const float var  = fmaxf(g_sumsq[tid] * invN - mean * mean, 0.0f);
        const float inv  = rsqrtf(var + 1e-5f);
        const float z    = (0.0f - mean) * inv;
        mm[tid] = mean;
        iv[tid] = inv;
        zz[tid] = (z >= 0.0f) ? z : 0.1f * z;
    }
    __syncthreads();

    {
        float4* __restrict__ out4 = reinterpret_cast<float4*>(out);
        const int c4 = (lane & 15) * 4;
        const float4 vz = make_float4(zz[c4], zz[c4 + 1], zz[c4 + 2], zz[c4 + 3]);
        const int ngrp = (N + 31) >> 5;   // 32-row groups

        for (int g = gwarp; g < ngrp; g += TOTAL_WARPS) {
            const int r0 = g * 32;
            const int fn = r0 + lane;
            const int f  = (fn < N) ? g_flag[fn] : 0;   // one coalesced load per warp
            const unsigned hits = __ballot_sync(FULL, f != 0);

            if (hits == 0 && r0 + 32 <= N) {
                const long base = (long)g * 512;        // float4 units (32 rows * 16)
#pragma unroll
                for (int j = 0; j < 16; j++)
                    out4[base + j * 32 + lane] = vz;
            } else {
                const int rend = min(r0 + 32, N);
                for (int r = r0; r < rend; r++) {
                    const int fr = __shfl_sync(FULL, f, r - r0);
                    float a0, a1;
                    if (fr) {
                        const float v0 = g_val[(long)r * CH + lane];
                        const float v1 = g_val[(long)r * CH + lane + 32];
                        a0 = (v0 - mm[lane])      * iv[lane];
                        a1 = (v1 - mm[lane + 32]) * iv[lane + 32];
                        a0 = (a0 >= 0.0f) ? a0 : 0.1f * a0;
                        a1 = (a1 >= 0.0f) ? a1 : 0.1f * a1;
                    } else {
                        a0 = zz[lane];
                        a1 = zz[lane + 32];
                    }
                    out[(long)r * CH + lane]      = a0;
                    out[(long)r * CH + lane + 32] = a1;
                }
            }
        }
    }
}

// ---------------- launch: ONE kernel ----------------
extern "C" void kernel_launch(void* const* d_in, const int* in_sizes, int n_in,
                              void* d_out, int out_size) {
    const float* q_pts = (const float*)d_in[0];
    const float* s_pts = (const float*)d_in[1];
    const int*   inds  = (const int*)  d_in[2];
    const float* x     = (const float*)d_in[3];
    const float* kp    = (const float*)d_in[4];
    const float* W     = (const float*)d_in[5];
    float* out = (float*)d_out;

    const int N = in_sizes[0] / 3;

    fused_kernel<<<NBLOCKS, NTHREADS>>>(q_pts, s_pts, inds, x, kp, W, out, N);
}

// round 13
// speedup vs baseline: 1.0732x; 1.0385x over previous
#include <cuda_runtime.h>
#include <math.h>

// Problem shape (fixed by dataset): N=100000, H=32, K=15, C_in=C_out=64
#define MAXN 100000
#define NB_H 32
#define KPTS 15
#define CH   64

#define NBLOCKS       592                // 148 SMs x 4 (co-resident via __launch_bounds__(256,4))
#define NTHREADS      256
#define TOTAL_THREADS (NBLOCKS * NTHREADS)
#define TOTAL_WARPS   (NBLOCKS * 8)

// Scratch (__device__ globals: allocation-free rule)
__device__ float4 g_pts4[MAXN];      // s_pts packed as float4 (w unused)
__device__ float  g_val[MAXN * CH];  // raw kpconv rows for flagged points
__device__ int    g_flag[MAXN];      // 1 if candidate row
__device__ float  g_sum[CH];
__device__ float  g_sumsq[CH];
// software grid barrier (self-resetting, safe across graph replays)
__device__ int          g_bar_count = 0;
__device__ volatile int g_bar_gen   = 0;

static __host__ __device__ __forceinline__ float kp_extent() {
    return (float)(0.1 * 1.2 / 2.5);
}

static __device__ __forceinline__ void grid_sync() {
    __threadfence();
    __syncthreads();
    if (threadIdx.x == 0) {
        const int gen = g_bar_gen;
        if (atomicAdd(&g_bar_count, 1) == NBLOCKS - 1) {
            g_bar_count = 0;
            __threadfence();
            g_bar_gen = gen + 1;
        } else {
            while (g_bar_gen == gen) { __nanosleep(32); }
        }
    }
    __syncthreads();
}

__global__ void __launch_bounds__(NTHREADS, 4) fused_kernel(
    const float* __restrict__ q_pts,
    const float* __restrict__ s_pts,
    const int*   __restrict__ inds,
    const float* __restrict__ x,
    const float* __restrict__ kp,
    const float* __restrict__ W,    // [K, C, C]
    float* __restrict__ out, int N)
{
    __shared__ float sw[8][KPTS][CH];        // 30 KB, heavy-phase staging
    __shared__ float mm[CH], iv[CH], zz[CH]; // phase-C stats

    const int tid   = threadIdx.x;
    const int warp  = tid >> 5;
    const int lane  = tid & 31;
    const int gtid  = blockIdx.x * NTHREADS + tid;
    const int gwarp = blockIdx.x * 8 + warp;
    const unsigned FULL = 0xffffffffu;

    // conservative candidate threshold^2 (broadcast L1/L2 loads)
    float thr2;
    {
        float mx2 = 0.0f;
#pragma unroll
        for (int k = 0; k < KPTS; k++) {
            const float a = __ldg(kp + 3*k), b = __ldg(kp + 3*k + 1), c = __ldg(kp + 3*k + 2);
            mx2 = fmaxf(mx2, fmaf(a, a, fmaf(b, b, c * c)));
        }
        const float t = (kp_extent() + sqrtf(mx2)) * 1.0002f + 1e-6f;  // false positives ok
        thr2 = t * t;
    }

    // ---------------- Phase A: pack s_pts (vectorized float4), zero flags/sums ----------------
    {
        const float4* __restrict__ s4 = reinterpret_cast<const float4*>(s_pts);
        const int nq = N >> 2;   // groups of 4 points (100000 -> 25000, no remainder)
        for (int i = gtid; i < nq; i += TOTAL_THREADS) {
            const float4 a = __ldg(s4 + (long)i * 3);
            const float4 b = __ldg(s4 + (long)i * 3 + 1);
            const float4 c = __ldg(s4 + (long)i * 3 + 2);
            const int p = i << 2;
            g_pts4[p]     = make_float4(a.x, a.y, a.z, 0.0f);
            g_pts4[p + 1] = make_float4(a.w, b.x, b.y, 0.0f);
            g_pts4[p + 2] = make_float4(b.z, b.w, c.x, 0.0f);
            g_pts4[p + 3] = make_float4(c.y, c.z, c.w, 0.0f);
            *reinterpret_cast<int4*>(&g_flag[p]) = make_int4(0, 0, 0, 0);
        }
        for (int i = (nq << 2) + gtid; i < N; i += TOTAL_THREADS) {   // generic tail
            g_flag[i] = 0;
            g_pts4[i] = make_float4(__ldg(s_pts + 3*i), __ldg(s_pts + 3*i + 1),
                                    __ldg(s_pts + 3*i + 2), 0.0f);
        }
        if (blockIdx.x == 0 && tid < CH) { g_sum[tid] = 0.0f; g_sumsq[tid] = 0.0f; }
    }
    grid_sync();

    // ------- Phase B: detect. thread-per-quad (MLP=4), float4 gathers, flags only -------
    {
        const int nquad = N * (NB_H / 4);   // 800000 int4 quads
        for (int t = gtid; t < nquad; t += TOTAL_THREADS) {
            const int n = t >> 3;           // 8 quads per point; q loads broadcast in-warp
            const float qx = __ldg(q_pts + 3*n);
            const float qy = __ldg(q_pts + 3*n + 1);
            const float qz = __ldg(q_pts + 3*n + 2);

            const int4 iv4 = __ldg(reinterpret_cast<const int4*>(inds) + t);

            // dataset guarantees idx in [0, N): no bounds checks (heavy path re-verifies)
            const float4 p0 = __ldg(&g_pts4[iv4.x]);
            const float4 p1 = __ldg(&g_pts4[iv4.y]);
            const float4 p2 = __ldg(&g_pts4[iv4.z]);
            const float4 p3 = __ldg(&g_pts4[iv4.w]);

            float dx, dy, dz;
            bool any = false;
            dx = p0.x - qx; dy = p0.y - qy; dz = p0.z - qz;
            any |= (fmaf(dx, dx, fmaf(dy, dy, dz * dz)) < thr2);
            dx = p1.x - qx; dy = p1.y - qy; dz = p1.z - qz;
            any |= (fmaf(dx, dx, fmaf(dy, dy, dz * dz)) < thr2);
            dx = p2.x - qx; dy = p2.y - qy; dz = p2.z - qz;
            any |= (fmaf(dx, dx, fmaf(dy, dy, dz * dz)) < thr2);
            dx = p3.x - qx; dy = p3.y - qy; dz = p3.z - qz;
            any |= (fmaf(dx, dx, fmaf(dy, dy, dz * dz)) < thr2);

            if (any) g_flag[n] = 1;         // racy same-value store: benign
        }
    }
    grid_sync();

    // ---------------- Phase B2: heavy. ballot-scan flags, exact KPConv per hit ----------------
    {
        const float EXT  = kp_extent();
        const float EXT2 = EXT * EXT;
        const float INVE = 1.0f / EXT;

        const int ngrp = (N + 31) >> 5;
        for (int g = gwarp; g < ngrp; g += TOTAL_WARPS) {
            const int fn = g * 32 + lane;
            const int f = (fn < N) ? g_flag[fn] : 0;
            unsigned hits = __ballot_sync(FULL, f != 0);

            while (hits) {
                const int bit = __ffs(hits) - 1;
                hits &= (hits - 1);
                const int n = g * 32 + bit;

                const float qx = __ldg(q_pts + 3*n);
                const float qy = __ldg(q_pts + 3*n + 1);
                const float qz = __ldg(q_pts + 3*n + 2);

                const int idx = __ldg(inds + (long)n * NB_H + lane);
                const bool valid = ((unsigned)idx < (unsigned)N);
                float nx = 1e9f, ny = 1e9f, nz = 1e9f;
                if (valid) {
                    const float4 p = __ldg(&g_pts4[idx]);
                    nx = p.x - qx; ny = p.y - qy; nz = p.z - qz;
                }
                const float r2 = fmaf(nx, nx, fmaf(ny, ny, nz * nz));
                unsigned mask = __ballot_sync(FULL, valid && (r2 < thr2));

                float acc0[KPTS], acc1[KPTS];
#pragma unroll
                for (int k = 0; k < KPTS; k++) { acc0[k] = 0.0f; acc1[k] = 0.0f; }

                unsigned m = mask;
                while (m) {
                    const int hs = __ffs(m) - 1;
                    m &= (m - 1);
                    const int   sidx = __shfl_sync(FULL, idx, hs);
                    const float bx = __shfl_sync(FULL, nx, hs);
                    const float by = __shfl_sync(FULL, ny, hs);
                    const float bz = __shfl_sync(FULL, nz, hs);
                    const float xv0 = __ldg(x + (long)sidx * CH + lane);
                    const float xv1 = __ldg(x + (long)sidx * CH + lane + 32);
#pragma unroll
                    for (int k = 0; k < KPTS; k++) {
                        const float dx = bx - __ldg(kp + 3*k);
                        const float dy = by - __ldg(kp + 3*k + 1);
                        const float dz = bz - __ldg(kp + 3*k + 2);
                        const float d2 = fmaf(dx, dx, fmaf(dy, dy, dz * dz));
                        if (d2 < EXT2) {
                            const float w = fmaxf(1.0f - sqrtf(d2) * INVE, 0.0f);
                            acc0[k] = fmaf(w, xv0, acc0[k]);
                            acc1[k] = fmaf(w, xv1, acc1[k]);
                        }
                    }
                }

                unsigned kmask = 0;
#pragma unroll
                for (int k = 0; k < KPTS; k++) {
                    sw[warp][k][lane]      = acc0[k];
                    sw[warp][k][lane + 32] = acc1[k];
                    if (__ballot_sync(FULL, (acc0[k] != 0.0f) || (acc1[k] != 0.0f)))
                        kmask |= (1u << k);
                }
                __syncwarp();

                float o0 = 0.0f, o1 = 0.0f;
                for (int k = 0; k < KPTS; k++) {
                    if (!(kmask & (1u << k))) continue;
                    const float* Wk = W + (long)k * CH * CH;
#pragma unroll 8
                    for (int c = 0; c < CH; c++) {
                        const float wv = sw[warp][k][c];
                        o0 = fmaf(wv, __ldg(Wk + c * CH + lane),      o0);
                        o1 = fmaf(wv, __ldg(Wk + c * CH + lane + 32), o1);
                    }
                }
                __syncwarp();

                g_val[(long)n * CH + lane]      = o0;
                g_val[(long)n * CH + lane + 32] = o1;
                atomicAdd(&g_sum[lane],        o0);
                atomicAdd(&g_sum[lane + 32],   o1);
                atomicAdd(&g_sumsq[lane],      o0 * o0);
                atomicAdd(&g_sumsq[lane + 32], o1 * o1);
            }
        }
    }
    grid_sync();

    // ---------------- Phase C: finalize stats, stream output ----------------
    if (tid < CH) {
        const float invN = 1.0f / (float)N;
        const float mean = g_sum[tid] * invN;
        const float var  = fmaxf(g_sumsq[tid] * invN - mean * mean, 0.0f);
        const float inv  = rsqrtf(var + 1e-5f);
        const float z    = (0.0f - mean) * inv;
        mm[tid] = mean;
        iv[tid] = inv;
        zz[tid] = (z >= 0.0f) ? z : 0.1f * z;
    }
    __syncthreads();

    {
        float4* __restrict__ out4 = reinterpret_cast<float4*>(out);
        const int c4 = (lane & 15) * 4;
        const float4 vz = make_float4(zz[c4], zz[c4 + 1], zz[c4 + 2], zz[c4 + 3]);
        const int ngrp = (N + 31) >> 5;   // 32-row groups

        for (int g = gwarp; g < ngrp; g += TOTAL_WARPS) {
            const int r0 = g * 32;
            const int fn = r0 + lane;
            const int f  = (fn < N) ? g_flag[fn] : 0;   // one coalesced load per warp
            const unsigned hits = __ballot_sync(FULL, f != 0);

            if (hits == 0 && r0 + 32 <= N) {
                const long base = (long)g * 512;        // float4 units (32 rows * 16)
#pragma unroll
                for (int j = 0; j < 16; j++)
                    out4[base + j * 32 + lane] = vz;
            } else {
                const int rend = min(r0 + 32, N);
                for (int r = r0; r < rend; r++) {
                    const int fr = __shfl_sync(FULL, f, r - r0);
                    float a0, a1;
                    if (fr) {
                        const float v0 = g_val[(long)r * CH + lane];
                        const float v1 = g_val[(long)r * CH + lane + 32];
                        a0 = (v0 - mm[lane])      * iv[lane];
                        a1 = (v1 - mm[lane + 32]) * iv[lane + 32];
                        a0 = (a0 >= 0.0f) ? a0 : 0.1f * a0;
                        a1 = (a1 >= 0.0f) ? a1 : 0.1f * a1;
                    } else {
                        a0 = zz[lane];
                        a1 = zz[lane + 32];
                    }
                    out[(long)r * CH + lane]      = a0;
                    out[(long)r * CH + lane + 32] = a1;
                }
            }
        }
    }
}

// ---------------- launch: ONE kernel ----------------
extern "C" void kernel_launch(void* const* d_in, const int* in_sizes, int n_in,
                              void* d_out, int out_size) {
    const float* q_pts = (const float*)d_in[0];
    const float* s_pts = (const float*)d_in[1];
    const int*   inds  = (const int*)  d_in[2];
    const float* x     = (const float*)d_in[3];
    const float* kp    = (const float*)d_in[4];
    const float* W     = (const float*)d_in[5];
    float* out = (float*)d_out;

    const int N = in_sizes[0] / 3;

    fused_kernel<<<NBLOCKS, NTHREADS>>>(q_pts, s_pts, inds, x, kp, W, out, N);
}